// round 3
// baseline (speedup 1.0000x reference)
#include <cuda_runtime.h>
#include <cuda_fp16.h>
#include <cstdint>

// ============================================================
// EdgeUpdate fused MLP via legacy mma.sync (sm_103 non-'a' target:
// no tcgen05 available through this toolchain path).
//   X[128,192]f16 @ W1[128,192]^T -> D1 (f32 frags)
//   H = shifted_softplus(D1+b1) -> f16 SMEM
//   H[128,128] @ W2[64,128]^T -> out = D2+b2 (f32)
// Persistent 148 CTAs x 256 threads, warp tiles 32x64 / 32x32.
// NOTE: edges tensor is int32 (JAX default x64-disabled downcasts
// the reference's jnp.int64 to int32) -> read as int2.
// ============================================================

#define XSTR 400   // bytes per row, 192 f16 padded (mult of 16, stride%32banks=4)
#define HSTR 272   // bytes per row, 128 f16 padded

#define SO_X   0
#define SO_W1  (128 * XSTR)            // 51200
#define SO_W2  (SO_W1 + 128 * XSTR)    // 102400
#define SO_H   (SO_W2 + 64 * HSTR)     // 119808
#define SO_B1  (SO_H + 128 * HSTR)     // 154624
#define SO_B2  (SO_B1 + 512)
#define SMEM_TOTAL (SO_B2 + 256 + 128) // ~155.8 KB

__device__ __forceinline__ uint32_t s2u(const void* p) {
    uint32_t a;
    asm("{ .reg .u64 t; cvta.to.shared.u64 t, %1; cvt.u32.u64 %0, t; }"
        : "=r"(a) : "l"(p));
    return a;
}

__device__ __forceinline__ uint32_t pkh2(float lo, float hi) {
    uint32_t r;
    asm("cvt.rn.f16x2.f32 %0, %1, %2;" : "=r"(r) : "f"(hi), "f"(lo));
    return r;
}

__device__ __forceinline__ void ldm4(uint32_t* r, uint32_t addr) {
    asm volatile("ldmatrix.sync.aligned.m8n8.x4.shared.b16 {%0,%1,%2,%3}, [%4];"
                 : "=r"(r[0]), "=r"(r[1]), "=r"(r[2]), "=r"(r[3]) : "r"(addr));
}

__device__ __forceinline__ void mma16816(float* d, const uint32_t* a,
                                         uint32_t b0, uint32_t b1) {
    asm volatile(
        "mma.sync.aligned.m16n8k16.row.col.f32.f16.f16.f32 "
        "{%0,%1,%2,%3}, {%4,%5,%6,%7}, {%8,%9}, {%0,%1,%2,%3};"
        : "+f"(d[0]), "+f"(d[1]), "+f"(d[2]), "+f"(d[3])
        : "r"(a[0]), "r"(a[1]), "r"(a[2]), "r"(a[3]), "r"(b0), "r"(b1));
}

// shifted softplus: softplus(x) - ln2 = max(x,0) + ln(1+e^{-|x|}) - ln2
__device__ __forceinline__ float ssp(float x) {
    float e = __expf(-fabsf(x));
    float l = __log2f(1.0f + e);
    return fmaxf(x, 0.0f) + 0.6931471805599453f * (l - 1.0f);
}

__global__ void __launch_bounds__(256, 1)
edge_update_kernel(const float* __restrict__ edge_state,
                   const int* __restrict__ edges,
                   const float* __restrict__ node_state,
                   const float* __restrict__ W1, const float* __restrict__ b1,
                   const float* __restrict__ W2, const float* __restrict__ b2,
                   float* __restrict__ out, int E) {
    extern __shared__ __align__(128) char smem[];
    uint32_t sb = s2u(smem);
    int tid = threadIdx.x;
    int lane = tid & 31, w = tid >> 5;

    // ---- one-time: stage weights (f32 -> f16) + biases into SMEM ----
    for (int i = tid; i < 128 * 192; i += 256) {
        int n = i / 192, k = i - n * 192;
        *(half*)(smem + SO_W1 + n * XSTR + k * 2) = __float2half_rn(W1[i]);
    }
    for (int i = tid; i < 64 * 128; i += 256) {
        int n = i >> 7, k = i & 127;
        *(half*)(smem + SO_W2 + n * HSTR + k * 2) = __float2half_rn(W2[i]);
    }
    if (tid < 128) ((float*)(smem + SO_B1))[tid] = b1[tid];
    if (tid < 64)  ((float*)(smem + SO_B2))[tid] = b2[tid];
    __syncthreads();

    // warp tiling: 4 m-groups x 2 n-groups
    const int m0  = (w & 3) * 32;   // 32 rows per warp
    const int n0  = (w >> 2) * 64;  // GEMM1: 64 cols per warp
    const int n02 = (w >> 2) * 32;  // GEMM2: 32 cols per warp

    // per-lane bias pairs (loop-invariant)
    float2 b1v[8], b2v[4];
    {
        const float* b1s = (const float*)(smem + SO_B1);
        const float* b2s = (const float*)(smem + SO_B2);
        int cb = 2 * (lane & 3);
#pragma unroll
        for (int nt = 0; nt < 8; nt++) {
            int c = n0 + nt * 8 + cb;
            b1v[nt] = make_float2(b1s[c], b1s[c + 1]);
        }
#pragma unroll
        for (int nt = 0; nt < 4; nt++) {
            int c = n02 + nt * 8 + cb;
            b2v[nt] = make_float2(b2s[c], b2s[c + 1]);
        }
    }

    // ldmatrix per-lane address components
    const int a_r = lane & 15;                       // A: row within 16
    const int a_c = (lane >> 4) << 3;                // A: k offset 0/8
    const int b_r = ((lane >> 4) << 3) + (lane & 7); // B: n-row within 16
    const int b_c = ((lane >> 3) & 1) << 3;          // B: k offset 0/8

    uint32_t aX[2], aH[2], bW1[4], bW2[2];
#pragma unroll
    for (int mt = 0; mt < 2; mt++) {
        aX[mt] = sb + SO_X + (uint32_t)(m0 + mt * 16 + a_r) * XSTR + a_c * 2;
        aH[mt] = sb + SO_H + (uint32_t)(m0 + mt * 16 + a_r) * HSTR + a_c * 2;
    }
#pragma unroll
    for (int np = 0; np < 4; np++)
        bW1[np] = sb + SO_W1 + (uint32_t)(n0 + np * 16 + b_r) * XSTR + b_c * 2;
#pragma unroll
    for (int np = 0; np < 2; np++)
        bW2[np] = sb + SO_W2 + (uint32_t)(n02 + np * 16 + b_r) * HSTR + b_c * 2;

    const int act_r = lane >> 2;
    const int act_c = 2 * (lane & 3);

    int ntiles = (E + 127) >> 7;
    for (int t = blockIdx.x; t < ntiles; t += gridDim.x) {
        // ================= gather -> f16 X tile =================
        {
            int row = tid & 127, seg = tid >> 7;
            long long e = (long long)t * 128 + row;
            long long ec = (e < E) ? e : (long long)(E - 1);
            int2 np2 = ((const int2*)edges)[ec];   // int32 node indices
            uint32_t xr = sb + SO_X + (uint32_t)row * XSTR;
            if (seg == 0) {
                const float4* p0 = (const float4*)(node_state + (long long)np2.x * 64);
#pragma unroll
                for (int j = 0; j < 8; j++) {
                    float4 a = p0[2 * j], c = p0[2 * j + 1];
                    uint32_t q0 = pkh2(a.x, a.y), q1 = pkh2(a.z, a.w);
                    uint32_t q2 = pkh2(c.x, c.y), q3 = pkh2(c.z, c.w);
                    asm volatile("st.shared.v4.b32 [%0],{%1,%2,%3,%4};"
                                 :: "r"(xr + j * 16), "r"(q0), "r"(q1),
                                    "r"(q2), "r"(q3) : "memory");
                }
                const float4* p1 = (const float4*)(node_state + (long long)np2.y * 64);
#pragma unroll
                for (int j = 0; j < 4; j++) {
                    float4 a = p1[2 * j], c = p1[2 * j + 1];
                    uint32_t q0 = pkh2(a.x, a.y), q1 = pkh2(a.z, a.w);
                    uint32_t q2 = pkh2(c.x, c.y), q3 = pkh2(c.z, c.w);
                    asm volatile("st.shared.v4.b32 [%0],{%1,%2,%3,%4};"
                                 :: "r"(xr + 128 + j * 16), "r"(q0), "r"(q1),
                                    "r"(q2), "r"(q3) : "memory");
                }
            } else {
                const float4* p1 = (const float4*)(node_state + (long long)np2.y * 64);
#pragma unroll
                for (int j = 0; j < 4; j++) {
                    float4 a = p1[8 + 2 * j], c = p1[9 + 2 * j];
                    uint32_t q0 = pkh2(a.x, a.y), q1 = pkh2(a.z, a.w);
                    uint32_t q2 = pkh2(c.x, c.y), q3 = pkh2(c.z, c.w);
                    asm volatile("st.shared.v4.b32 [%0],{%1,%2,%3,%4};"
                                 :: "r"(xr + 192 + j * 16), "r"(q0), "r"(q1),
                                    "r"(q2), "r"(q3) : "memory");
                }
                const float4* pe = (const float4*)(edge_state + ec * 64);
#pragma unroll
                for (int j = 0; j < 8; j++) {
                    float4 a = pe[2 * j], c = pe[2 * j + 1];
                    uint32_t q0 = pkh2(a.x, a.y), q1 = pkh2(a.z, a.w);
                    uint32_t q2 = pkh2(c.x, c.y), q3 = pkh2(c.z, c.w);
                    asm volatile("st.shared.v4.b32 [%0],{%1,%2,%3,%4};"
                                 :: "r"(xr + 256 + j * 16), "r"(q0), "r"(q1),
                                    "r"(q2), "r"(q3) : "memory");
                }
            }
        }
        __syncthreads();

        // ================= GEMM1: 32x128, K=192 =================
        float acc[2][8][4];
#pragma unroll
        for (int mt = 0; mt < 2; mt++)
#pragma unroll
            for (int nt = 0; nt < 8; nt++)
#pragma unroll
                for (int q = 0; q < 4; q++) acc[mt][nt][q] = 0.0f;

#pragma unroll
        for (int k = 0; k < 12; k++) {
            uint32_t A0[4], A1[4], B[4][4];
            ldm4(A0, aX[0] + k * 32);
            ldm4(A1, aX[1] + k * 32);
#pragma unroll
            for (int np = 0; np < 4; np++) ldm4(B[np], bW1[np] + k * 32);
#pragma unroll
            for (int np = 0; np < 4; np++) {
#pragma unroll
                for (int h = 0; h < 2; h++) {
                    mma16816(acc[0][np * 2 + h], A0, B[np][2 * h], B[np][2 * h + 1]);
                    mma16816(acc[1][np * 2 + h], A1, B[np][2 * h], B[np][2 * h + 1]);
                }
            }
        }

        // ============ activation -> f16 H tile ============
#pragma unroll
        for (int mt = 0; mt < 2; mt++) {
            uint32_t ha = sb + SO_H
                        + (uint32_t)(m0 + mt * 16 + act_r) * HSTR
                        + (uint32_t)(n0 + act_c) * 2;
#pragma unroll
            for (int nt = 0; nt < 8; nt++) {
                float x0 = acc[mt][nt][0] + b1v[nt].x;
                float x1 = acc[mt][nt][1] + b1v[nt].y;
                float x2 = acc[mt][nt][2] + b1v[nt].x;
                float x3 = acc[mt][nt][3] + b1v[nt].y;
                uint32_t h01 = pkh2(ssp(x0), ssp(x1));
                uint32_t h23 = pkh2(ssp(x2), ssp(x3));
                asm volatile("st.shared.b32 [%0], %1;"
                             :: "r"(ha + nt * 16), "r"(h01) : "memory");
                asm volatile("st.shared.b32 [%0], %1;"
                             :: "r"(ha + nt * 16 + 8 * HSTR), "r"(h23) : "memory");
            }
        }
        __syncthreads();

        // ================= GEMM2: 32x32, K=128 =================
        float acc2[2][4][4];
#pragma unroll
        for (int mt = 0; mt < 2; mt++)
#pragma unroll
            for (int nt = 0; nt < 4; nt++)
#pragma unroll
                for (int q = 0; q < 4; q++) acc2[mt][nt][q] = 0.0f;

#pragma unroll
        for (int k = 0; k < 8; k++) {
            uint32_t A0[4], A1[4], B[2][4];
            ldm4(A0, aH[0] + k * 32);
            ldm4(A1, aH[1] + k * 32);
            ldm4(B[0], bW2[0] + k * 32);
            ldm4(B[1], bW2[1] + k * 32);
#pragma unroll
            for (int np = 0; np < 2; np++) {
#pragma unroll
                for (int h = 0; h < 2; h++) {
                    mma16816(acc2[0][np * 2 + h], A0, B[np][2 * h], B[np][2 * h + 1]);
                    mma16816(acc2[1][np * 2 + h], A1, B[np][2 * h], B[np][2 * h + 1]);
                }
            }
        }

        // ================= epilogue: out = D2 + b2 =================
        {
            long long ebase = (long long)t * 128 + m0 + act_r;
#pragma unroll
            for (int mt = 0; mt < 2; mt++) {
                long long r0e = ebase + mt * 16;
#pragma unroll
                for (int nt = 0; nt < 4; nt++) {
                    int c = n02 + nt * 8 + act_c;
                    if (r0e < E) {
                        float2 v;
                        v.x = acc2[mt][nt][0] + b2v[nt].x;
                        v.y = acc2[mt][nt][1] + b2v[nt].y;
                        *(float2*)(out + r0e * 64 + c) = v;
                    }
                    if (r0e + 8 < E) {
                        float2 v;
                        v.x = acc2[mt][nt][2] + b2v[nt].x;
                        v.y = acc2[mt][nt][3] + b2v[nt].y;
                        *(float2*)(out + (r0e + 8) * 64 + c) = v;
                    }
                }
            }
        }
        __syncthreads();
    }
}

extern "C" void kernel_launch(void* const* d_in, const int* in_sizes, int n_in,
                              void* d_out, int out_size) {
    const float* edge_state = (const float*)d_in[0];
    const int*   edges      = (const int*)d_in[1];
    const float* node_state = (const float*)d_in[2];
    const float* W1         = (const float*)d_in[3];
    const float* b1         = (const float*)d_in[4];
    const float* W2         = (const float*)d_in[5];
    const float* b2         = (const float*)d_in[6];
    float*       out        = (float*)d_out;
    int E = in_sizes[0] / 64;

    cudaFuncSetAttribute(edge_update_kernel,
                         cudaFuncAttributeMaxDynamicSharedMemorySize, SMEM_TOTAL);
    edge_update_kernel<<<148, 256, SMEM_TOTAL>>>(edge_state, edges, node_state,
                                                 W1, b1, W2, b2, out, E);
}

// round 4
// speedup vs baseline: 1.2839x; 1.2839x over previous
#include <cuda_runtime.h>
#include <cuda_fp16.h>
#include <cstdint>

// ============================================================
// EdgeUpdate fused MLP via legacy mma.sync (sm_103 non-'a' target).
//   X[128,192]f16 @ W1[128,192]^T -> D1 (f32 frags)
//   H = shifted_softplus(D1+b1) -> f16 SMEM
//   H[128,128] @ W2[64,128]^T -> out = D2+b2 (f32)
// Persistent 148 CTAs x 256 threads, warp tiles 32x64 / 32x32.
// R4: coalesced gather (half-warp per 256B row segment; 4 wavefronts
// per warp-load instead of 32) + one fewer barrier per tile.
// ============================================================

#define XSTR 400   // bytes per row, 192 f16 padded
#define HSTR 272   // bytes per row, 128 f16 padded

#define SO_X   0
#define SO_W1  (128 * XSTR)            // 51200
#define SO_W2  (SO_W1 + 128 * XSTR)    // 102400
#define SO_H   (SO_W2 + 64 * HSTR)     // 119808
#define SO_B1  (SO_H + 128 * HSTR)     // 154624
#define SO_B2  (SO_B1 + 512)
#define SMEM_TOTAL (SO_B2 + 256 + 128) // ~155.8 KB

__device__ __forceinline__ uint32_t s2u(const void* p) {
    uint32_t a;
    asm("{ .reg .u64 t; cvta.to.shared.u64 t, %1; cvt.u32.u64 %0, t; }"
        : "=r"(a) : "l"(p));
    return a;
}

__device__ __forceinline__ uint32_t pkh2(float lo, float hi) {
    uint32_t r;
    asm("cvt.rn.f16x2.f32 %0, %1, %2;" : "=r"(r) : "f"(hi), "f"(lo));
    return r;
}

__device__ __forceinline__ void ldm4(uint32_t* r, uint32_t addr) {
    asm volatile("ldmatrix.sync.aligned.m8n8.x4.shared.b16 {%0,%1,%2,%3}, [%4];"
                 : "=r"(r[0]), "=r"(r[1]), "=r"(r[2]), "=r"(r[3]) : "r"(addr));
}

__device__ __forceinline__ void mma16816(float* d, const uint32_t* a,
                                         uint32_t b0, uint32_t b1) {
    asm volatile(
        "mma.sync.aligned.m16n8k16.row.col.f32.f16.f16.f32 "
        "{%0,%1,%2,%3}, {%4,%5,%6,%7}, {%8,%9}, {%0,%1,%2,%3};"
        : "+f"(d[0]), "+f"(d[1]), "+f"(d[2]), "+f"(d[3])
        : "r"(a[0]), "r"(a[1]), "r"(a[2]), "r"(a[3]), "r"(b0), "r"(b1));
}

// shifted softplus: softplus(x) - ln2 = max(x,0) + ln(1+e^{-|x|}) - ln2
__device__ __forceinline__ float ssp(float x) {
    float e = __expf(-fabsf(x));
    float l = __log2f(1.0f + e);
    return fmaxf(x, 0.0f) + 0.6931471805599453f * (l - 1.0f);
}

__global__ void __launch_bounds__(256, 1)
edge_update_kernel(const float* __restrict__ edge_state,
                   const int* __restrict__ edges,
                   const float* __restrict__ node_state,
                   const float* __restrict__ W1, const float* __restrict__ b1,
                   const float* __restrict__ W2, const float* __restrict__ b2,
                   float* __restrict__ out, int E) {
    extern __shared__ __align__(128) char smem[];
    uint32_t sb = s2u(smem);
    int tid = threadIdx.x;
    int lane = tid & 31, w = tid >> 5;

    // ---- one-time: stage weights (f32 -> f16) + biases into SMEM ----
    for (int i = tid; i < 128 * 192; i += 256) {
        int n = i / 192, k = i - n * 192;
        *(half*)(smem + SO_W1 + n * XSTR + k * 2) = __float2half_rn(W1[i]);
    }
    for (int i = tid; i < 64 * 128; i += 256) {
        int n = i >> 7, k = i & 127;
        *(half*)(smem + SO_W2 + n * HSTR + k * 2) = __float2half_rn(W2[i]);
    }
    if (tid < 128) ((float*)(smem + SO_B1))[tid] = b1[tid];
    if (tid < 64)  ((float*)(smem + SO_B2))[tid] = b2[tid];
    __syncthreads();

    // warp tiling: 4 m-groups x 2 n-groups
    const int m0  = (w & 3) * 32;   // 32 rows per warp
    const int n0  = (w >> 2) * 64;  // GEMM1: 64 cols per warp
    const int n02 = (w >> 2) * 32;  // GEMM2: 32 cols per warp

    // per-lane bias pairs (loop-invariant)
    float2 b1v[8], b2v[4];
    {
        const float* b1s = (const float*)(smem + SO_B1);
        const float* b2s = (const float*)(smem + SO_B2);
        int cb = 2 * (lane & 3);
#pragma unroll
        for (int nt = 0; nt < 8; nt++) {
            int c = n0 + nt * 8 + cb;
            b1v[nt] = make_float2(b1s[c], b1s[c + 1]);
        }
#pragma unroll
        for (int nt = 0; nt < 4; nt++) {
            int c = n02 + nt * 8 + cb;
            b2v[nt] = make_float2(b2s[c], b2s[c + 1]);
        }
    }

    // ldmatrix per-lane address components
    const int a_r = lane & 15;                       // A: row within 16
    const int a_c = (lane >> 4) << 3;                // A: k offset 0/8
    const int b_r = ((lane >> 4) << 3) + (lane & 7); // B: n-row within 16
    const int b_c = ((lane >> 3) & 1) << 3;          // B: k offset 0/8

    uint32_t aX[2], aH[2], bW1[4], bW2[2];
#pragma unroll
    for (int mt = 0; mt < 2; mt++) {
        aX[mt] = sb + SO_X + (uint32_t)(m0 + mt * 16 + a_r) * XSTR + a_c * 2;
        aH[mt] = sb + SO_H + (uint32_t)(m0 + mt * 16 + a_r) * HSTR + a_c * 2;
    }
#pragma unroll
    for (int np = 0; np < 4; np++)
        bW1[np] = sb + SO_W1 + (uint32_t)(n0 + np * 16 + b_r) * XSTR + b_c * 2;
#pragma unroll
    for (int np = 0; np < 2; np++)
        bW2[np] = sb + SO_W2 + (uint32_t)(n02 + np * 16 + b_r) * HSTR + b_c * 2;

    const int act_r = lane >> 2;
    const int act_c = 2 * (lane & 3);

    // gather lane mapping: half-warp per row, lane li owns float4 #li of
    // each 64-float source segment (256B contiguous per 16 lanes).
    const int g_half = lane >> 4;        // 0/1: row parity within pair
    const int g_li   = lane & 15;        // float4 index within row segment

    int ntiles = (E + 127) >> 7;
    for (int t = blockIdx.x; t < ntiles; t += gridDim.x) {
        // ========== coalesced gather -> f16 X tile ==========
        // warp w handles rows [16w, 16w+16); per iter, 2 rows (one per half-warp)
#pragma unroll
        for (int it = 0; it < 8; it++) {
            int row = w * 16 + it * 2 + g_half;
            long long e = (long long)t * 128 + row;
            long long ec = (e < E) ? e : (long long)(E - 1);
            int2 np2 = ((const int2*)edges)[ec];
            uint32_t xr = sb + SO_X + (uint32_t)row * XSTR + (uint32_t)g_li * 8u;
            float4 v0 = ((const float4*)(node_state + (long long)np2.x * 64))[g_li];
            float4 v1 = ((const float4*)(node_state + (long long)np2.y * 64))[g_li];
            float4 v2 = ((const float4*)(edge_state + ec * 64))[g_li];
            uint32_t a0 = pkh2(v0.x, v0.y), a1 = pkh2(v0.z, v0.w);
            uint32_t c0 = pkh2(v1.x, v1.y), c1 = pkh2(v1.z, v1.w);
            uint32_t d0 = pkh2(v2.x, v2.y), d1 = pkh2(v2.z, v2.w);
            asm volatile("st.shared.v2.b32 [%0], {%1,%2};"
                         :: "r"(xr), "r"(a0), "r"(a1) : "memory");
            asm volatile("st.shared.v2.b32 [%0], {%1,%2};"
                         :: "r"(xr + 128), "r"(c0), "r"(c1) : "memory");
            asm volatile("st.shared.v2.b32 [%0], {%1,%2};"
                         :: "r"(xr + 256), "r"(d0), "r"(d1) : "memory");
        }
        __syncthreads();

        // ================= GEMM1: 32x128, K=192 =================
        float acc[2][8][4];
#pragma unroll
        for (int mt = 0; mt < 2; mt++)
#pragma unroll
            for (int nt = 0; nt < 8; nt++)
#pragma unroll
                for (int q = 0; q < 4; q++) acc[mt][nt][q] = 0.0f;

#pragma unroll
        for (int k = 0; k < 12; k++) {
            uint32_t A0[4], A1[4], B[4][4];
            ldm4(A0, aX[0] + k * 32);
            ldm4(A1, aX[1] + k * 32);
#pragma unroll
            for (int np = 0; np < 4; np++) ldm4(B[np], bW1[np] + k * 32);
#pragma unroll
            for (int np = 0; np < 4; np++) {
#pragma unroll
                for (int h = 0; h < 2; h++) {
                    mma16816(acc[0][np * 2 + h], A0, B[np][2 * h], B[np][2 * h + 1]);
                    mma16816(acc[1][np * 2 + h], A1, B[np][2 * h], B[np][2 * h + 1]);
                }
            }
        }

        // ============ activation -> f16 H tile ============
#pragma unroll
        for (int mt = 0; mt < 2; mt++) {
            uint32_t ha = sb + SO_H
                        + (uint32_t)(m0 + mt * 16 + act_r) * HSTR
                        + (uint32_t)(n0 + act_c) * 2;
#pragma unroll
            for (int nt = 0; nt < 8; nt++) {
                float x0 = acc[mt][nt][0] + b1v[nt].x;
                float x1 = acc[mt][nt][1] + b1v[nt].y;
                float x2 = acc[mt][nt][2] + b1v[nt].x;
                float x3 = acc[mt][nt][3] + b1v[nt].y;
                uint32_t h01 = pkh2(ssp(x0), ssp(x1));
                uint32_t h23 = pkh2(ssp(x2), ssp(x3));
                asm volatile("st.shared.b32 [%0], %1;"
                             :: "r"(ha + nt * 16), "r"(h01) : "memory");
                asm volatile("st.shared.b32 [%0], %1;"
                             :: "r"(ha + nt * 16 + 8 * HSTR), "r"(h23) : "memory");
            }
        }
        __syncthreads();

        // ================= GEMM2: 32x32, K=128 =================
        float acc2[2][4][4];
#pragma unroll
        for (int mt = 0; mt < 2; mt++)
#pragma unroll
            for (int nt = 0; nt < 4; nt++)
#pragma unroll
                for (int q = 0; q < 4; q++) acc2[mt][nt][q] = 0.0f;

#pragma unroll
        for (int k = 0; k < 8; k++) {
            uint32_t A0[4], A1[4], B[2][4];
            ldm4(A0, aH[0] + k * 32);
            ldm4(A1, aH[1] + k * 32);
            ldm4(B[0], bW2[0] + k * 32);
            ldm4(B[1], bW2[1] + k * 32);
#pragma unroll
            for (int np = 0; np < 2; np++) {
#pragma unroll
                for (int h = 0; h < 2; h++) {
                    mma16816(acc2[0][np * 2 + h], A0, B[np][2 * h], B[np][2 * h + 1]);
                    mma16816(acc2[1][np * 2 + h], A1, B[np][2 * h], B[np][2 * h + 1]);
                }
            }
        }

        // ================= epilogue: out = D2 + b2 =================
        // NOTE: no trailing __syncthreads() — next tile's X writes are
        // ordered against this tile's GEMM1 reads by the act-sync above,
        // and GEMM2 touches only H/W2.
        {
            long long ebase = (long long)t * 128 + m0 + act_r;
#pragma unroll
            for (int mt = 0; mt < 2; mt++) {
                long long r0e = ebase + mt * 16;
#pragma unroll
                for (int nt = 0; nt < 4; nt++) {
                    int c = n02 + nt * 8 + act_c;
                    if (r0e < E) {
                        float2 v;
                        v.x = acc2[mt][nt][0] + b2v[nt].x;
                        v.y = acc2[mt][nt][1] + b2v[nt].y;
                        *(float2*)(out + r0e * 64 + c) = v;
                    }
                    if (r0e + 8 < E) {
                        float2 v;
                        v.x = acc2[mt][nt][2] + b2v[nt].x;
                        v.y = acc2[mt][nt][3] + b2v[nt].y;
                        *(float2*)(out + (r0e + 8) * 64 + c) = v;
                    }
                }
            }
        }
    }
}

extern "C" void kernel_launch(void* const* d_in, const int* in_sizes, int n_in,
                              void* d_out, int out_size) {
    const float* edge_state = (const float*)d_in[0];
    const int*   edges      = (const int*)d_in[1];
    const float* node_state = (const float*)d_in[2];
    const float* W1         = (const float*)d_in[3];
    const float* b1         = (const float*)d_in[4];
    const float* W2         = (const float*)d_in[5];
    const float* b2         = (const float*)d_in[6];
    float*       out        = (float*)d_out;
    int E = in_sizes[0] / 64;

    cudaFuncSetAttribute(edge_update_kernel,
                         cudaFuncAttributeMaxDynamicSharedMemorySize, SMEM_TOTAL);
    edge_update_kernel<<<148, 256, SMEM_TOTAL>>>(edge_state, edges, node_state,
                                                 W1, b1, W2, b2, out, E);
}

// round 5
// speedup vs baseline: 1.5334x; 1.1943x over previous
#include <cuda_runtime.h>
#include <cuda_fp16.h>
#include <cstdint>

// ============================================================
// EdgeUpdate fused MLP via legacy mma.sync (sm_103 non-'a' target).
// R5: 2 CTAs/SM (256 thr, <=128 regs, ~110KB SMEM each), 64-row
// tiles, warp tiles 32x32 (GEMM1) / 32x16 (GEMM2). Cross-CTA phase
// overlap replaces software pipelining. Streaming hints on
// edge_state/out to keep node_state L2-resident.
// ============================================================

#define XSTR 400   // 192 f16 + 16B pad
#define HSTR 272   // 128 f16 + 16B pad

#define SO_X   0                       // 64 x XSTR  = 25600
#define SO_W1  (64 * XSTR)             // 128 x XSTR = 51200
#define SO_W2  (SO_W1 + 128 * XSTR)    // 64 x HSTR  = 17408
#define SO_H   (SO_W2 + 64 * HSTR)     // 64 x HSTR  = 17408
#define SO_B1  (SO_H + 64 * HSTR)
#define SO_B2  (SO_B1 + 512)
#define SMEM_TOTAL (SO_B2 + 256 + 128) // 112512 B -> 2 CTAs/SM

__device__ __forceinline__ uint32_t s2u(const void* p) {
    uint32_t a;
    asm("{ .reg .u64 t; cvta.to.shared.u64 t, %1; cvt.u32.u64 %0, t; }"
        : "=r"(a) : "l"(p));
    return a;
}

__device__ __forceinline__ uint32_t pkh2(float lo, float hi) {
    uint32_t r;
    asm("cvt.rn.f16x2.f32 %0, %1, %2;" : "=r"(r) : "f"(hi), "f"(lo));
    return r;
}

__device__ __forceinline__ void ldm4(uint32_t* r, uint32_t addr) {
    asm volatile("ldmatrix.sync.aligned.m8n8.x4.shared.b16 {%0,%1,%2,%3}, [%4];"
                 : "=r"(r[0]), "=r"(r[1]), "=r"(r[2]), "=r"(r[3]) : "r"(addr));
}

__device__ __forceinline__ void mma16816(float* d, const uint32_t* a,
                                         uint32_t b0, uint32_t b1) {
    asm volatile(
        "mma.sync.aligned.m16n8k16.row.col.f32.f16.f16.f32 "
        "{%0,%1,%2,%3}, {%4,%5,%6,%7}, {%8,%9}, {%0,%1,%2,%3};"
        : "+f"(d[0]), "+f"(d[1]), "+f"(d[2]), "+f"(d[3])
        : "r"(a[0]), "r"(a[1]), "r"(a[2]), "r"(a[3]), "r"(b0), "r"(b1));
}

// shifted softplus: softplus(x) - ln2 = max(x,0) + ln(1+e^{-|x|}) - ln2
__device__ __forceinline__ float ssp(float x) {
    float e = __expf(-fabsf(x));
    float l = __log2f(1.0f + e);
    return fmaxf(x, 0.0f) + 0.6931471805599453f * (l - 1.0f);
}

__global__ void __launch_bounds__(256, 2)
edge_update_kernel(const float* __restrict__ edge_state,
                   const int* __restrict__ edges,
                   const float* __restrict__ node_state,
                   const float* __restrict__ W1, const float* __restrict__ b1,
                   const float* __restrict__ W2, const float* __restrict__ b2,
                   float* __restrict__ out, int E) {
    extern __shared__ __align__(128) char smem[];
    uint32_t sb = s2u(smem);
    int tid = threadIdx.x;
    int lane = tid & 31, w = tid >> 5;

    // ---- one-time: stage weights (f32 -> f16) + biases into SMEM ----
    for (int i = tid; i < 128 * 192; i += 256) {
        int n = i / 192, k = i - n * 192;
        *(half*)(smem + SO_W1 + n * XSTR + k * 2) = __float2half_rn(W1[i]);
    }
    for (int i = tid; i < 64 * 128; i += 256) {
        int n = i >> 7, k = i & 127;
        *(half*)(smem + SO_W2 + n * HSTR + k * 2) = __float2half_rn(W2[i]);
    }
    if (tid < 128) ((float*)(smem + SO_B1))[tid] = b1[tid];
    if (tid < 64)  ((float*)(smem + SO_B2))[tid] = b2[tid];
    __syncthreads();

    // warp tiling: 2 m-groups x 4 n-groups over the 64x128 GEMM1 tile
    const int m0  = (w & 1) * 32;    // 32 rows per warp
    const int n0  = (w >> 1) * 32;   // GEMM1: 32 cols per warp
    const int n02 = (w >> 1) * 16;   // GEMM2: 16 cols per warp

    // per-lane bias pairs (loop-invariant)
    float2 b1v[4], b2v[2];
    {
        const float* b1s = (const float*)(smem + SO_B1);
        const float* b2s = (const float*)(smem + SO_B2);
        int cb = 2 * (lane & 3);
#pragma unroll
        for (int nt = 0; nt < 4; nt++) {
            int c = n0 + nt * 8 + cb;
            b1v[nt] = make_float2(b1s[c], b1s[c + 1]);
        }
#pragma unroll
        for (int nt = 0; nt < 2; nt++) {
            int c = n02 + nt * 8 + cb;
            b2v[nt] = make_float2(b2s[c], b2s[c + 1]);
        }
    }

    // ldmatrix per-lane address components
    const int a_r = lane & 15;                       // A: row within 16
    const int a_c = (lane >> 4) << 3;                // A: k offset 0/8
    const int b_r = ((lane >> 4) << 3) + (lane & 7); // B: n-row within 16
    const int b_c = ((lane >> 3) & 1) << 3;          // B: k offset 0/8

    uint32_t aX[2], aH[2], bW1[2], bW2;
#pragma unroll
    for (int mt = 0; mt < 2; mt++) {
        aX[mt] = sb + SO_X + (uint32_t)(m0 + mt * 16 + a_r) * XSTR + a_c * 2;
        aH[mt] = sb + SO_H + (uint32_t)(m0 + mt * 16 + a_r) * HSTR + a_c * 2;
    }
#pragma unroll
    for (int np = 0; np < 2; np++)
        bW1[np] = sb + SO_W1 + (uint32_t)(n0 + np * 16 + b_r) * XSTR + b_c * 2;
    bW2 = sb + SO_W2 + (uint32_t)(n02 + b_r) * HSTR + b_c * 2;

    const int act_r = lane >> 2;
    const int act_c = 2 * (lane & 3);

    // gather lane mapping: half-warp per row, lane li owns float4 #li
    const int g_half = lane >> 4;
    const int g_li   = lane & 15;

    int ntiles = (E + 63) >> 6;
    for (int t = blockIdx.x; t < ntiles; t += gridDim.x) {
        // ========== coalesced gather -> f16 X tile (64 rows) ==========
        // warp w handles rows [8w, 8w+8); per iter 2 rows (one per half-warp)
#pragma unroll
        for (int it = 0; it < 4; it++) {
            int row = w * 8 + it * 2 + g_half;
            long long e = (long long)t * 64 + row;
            long long ec = (e < E) ? e : (long long)(E - 1);
            int2 np2 = ((const int2*)edges)[ec];
            uint32_t xr = sb + SO_X + (uint32_t)row * XSTR + (uint32_t)g_li * 8u;
            float4 v0 = ((const float4*)(node_state + (long long)np2.x * 64))[g_li];
            float4 v1 = ((const float4*)(node_state + (long long)np2.y * 64))[g_li];
            float4 v2 = __ldcs((const float4*)(edge_state + ec * 64) + g_li);
            uint32_t a0 = pkh2(v0.x, v0.y), a1 = pkh2(v0.z, v0.w);
            uint32_t c0 = pkh2(v1.x, v1.y), c1 = pkh2(v1.z, v1.w);
            uint32_t d0 = pkh2(v2.x, v2.y), d1 = pkh2(v2.z, v2.w);
            asm volatile("st.shared.v2.b32 [%0], {%1,%2};"
                         :: "r"(xr), "r"(a0), "r"(a1) : "memory");
            asm volatile("st.shared.v2.b32 [%0], {%1,%2};"
                         :: "r"(xr + 128), "r"(c0), "r"(c1) : "memory");
            asm volatile("st.shared.v2.b32 [%0], {%1,%2};"
                         :: "r"(xr + 256), "r"(d0), "r"(d1) : "memory");
        }
        __syncthreads();

        // ================= GEMM1: 32x32, K=192 =================
        float acc[2][4][4];
#pragma unroll
        for (int mt = 0; mt < 2; mt++)
#pragma unroll
            for (int nt = 0; nt < 4; nt++)
#pragma unroll
                for (int q = 0; q < 4; q++) acc[mt][nt][q] = 0.0f;

#pragma unroll
        for (int k = 0; k < 12; k++) {
            uint32_t A0[4], A1[4], B[2][4];
            ldm4(A0, aX[0] + k * 32);
            ldm4(A1, aX[1] + k * 32);
            ldm4(B[0], bW1[0] + k * 32);
            ldm4(B[1], bW1[1] + k * 32);
#pragma unroll
            for (int np = 0; np < 2; np++) {
#pragma unroll
                for (int h = 0; h < 2; h++) {
                    mma16816(acc[0][np * 2 + h], A0, B[np][2 * h], B[np][2 * h + 1]);
                    mma16816(acc[1][np * 2 + h], A1, B[np][2 * h], B[np][2 * h + 1]);
                }
            }
        }

        // ============ activation -> f16 H tile ============
#pragma unroll
        for (int mt = 0; mt < 2; mt++) {
            uint32_t ha = sb + SO_H
                        + (uint32_t)(m0 + mt * 16 + act_r) * HSTR
                        + (uint32_t)(n0 + act_c) * 2;
#pragma unroll
            for (int nt = 0; nt < 4; nt++) {
                float x0 = acc[mt][nt][0] + b1v[nt].x;
                float x1 = acc[mt][nt][1] + b1v[nt].y;
                float x2 = acc[mt][nt][2] + b1v[nt].x;
                float x3 = acc[mt][nt][3] + b1v[nt].y;
                uint32_t h01 = pkh2(ssp(x0), ssp(x1));
                uint32_t h23 = pkh2(ssp(x2), ssp(x3));
                asm volatile("st.shared.b32 [%0], %1;"
                             :: "r"(ha + nt * 16), "r"(h01) : "memory");
                asm volatile("st.shared.b32 [%0], %1;"
                             :: "r"(ha + nt * 16 + 8 * HSTR), "r"(h23) : "memory");
            }
        }
        __syncthreads();

        // ================= GEMM2: 32x16, K=128 =================
        float acc2[2][2][4];
#pragma unroll
        for (int mt = 0; mt < 2; mt++)
#pragma unroll
            for (int nt = 0; nt < 2; nt++)
#pragma unroll
                for (int q = 0; q < 4; q++) acc2[mt][nt][q] = 0.0f;

#pragma unroll
        for (int k = 0; k < 8; k++) {
            uint32_t A0[4], A1[4], B[4];
            ldm4(A0, aH[0] + k * 32);
            ldm4(A1, aH[1] + k * 32);
            ldm4(B, bW2 + k * 32);
#pragma unroll
            for (int h = 0; h < 2; h++) {
                mma16816(acc2[0][h], A0, B[2 * h], B[2 * h + 1]);
                mma16816(acc2[1][h], A1, B[2 * h], B[2 * h + 1]);
            }
        }

        // ================= epilogue: out = D2 + b2 (streaming) ==========
        // no trailing sync: next gather's X writes are ordered against this
        // tile's GEMM1 reads by the act-sync; GEMM2 touches only H/W2, and
        // the next gather-sync orders H rewrites after all GEMM2 reads.
        {
            long long ebase = (long long)t * 64 + m0 + act_r;
#pragma unroll
            for (int mt = 0; mt < 2; mt++) {
                long long r0e = ebase + mt * 16;
#pragma unroll
                for (int nt = 0; nt < 2; nt++) {
                    int c = n02 + nt * 8 + act_c;
                    if (r0e < E) {
                        float2 v;
                        v.x = acc2[mt][nt][0] + b2v[nt].x;
                        v.y = acc2[mt][nt][1] + b2v[nt].y;
                        __stcs((float2*)(out + r0e * 64 + c), v);
                    }
                    if (r0e + 8 < E) {
                        float2 v;
                        v.x = acc2[mt][nt][2] + b2v[nt].x;
                        v.y = acc2[mt][nt][3] + b2v[nt].y;
                        __stcs((float2*)(out + (r0e + 8) * 64 + c), v);
                    }
                }
            }
        }
    }
}

extern "C" void kernel_launch(void* const* d_in, const int* in_sizes, int n_in,
                              void* d_out, int out_size) {
    const float* edge_state = (const float*)d_in[0];
    const int*   edges      = (const int*)d_in[1];
    const float* node_state = (const float*)d_in[2];
    const float* W1         = (const float*)d_in[3];
    const float* b1         = (const float*)d_in[4];
    const float* W2         = (const float*)d_in[5];
    const float* b2         = (const float*)d_in[6];
    float*       out        = (float*)d_out;
    int E = in_sizes[0] / 64;

    cudaFuncSetAttribute(edge_update_kernel,
                         cudaFuncAttributeMaxDynamicSharedMemorySize, SMEM_TOTAL);
    edge_update_kernel<<<296, 256, SMEM_TOTAL>>>(edge_state, edges, node_state,
                                                 W1, b1, W2, b2, out, E);
}

// round 6
// speedup vs baseline: 1.5415x; 1.0053x over previous
#include <cuda_runtime.h>
#include <cuda_fp16.h>
#include <cstdint>

// ============================================================
// EdgeUpdate fused MLP via legacy mma.sync (sm_103 non-'a' target).
// R6: warp-specialized producer/consumer. One 384-thread CTA/SM:
//   - 8 consumer warps: GEMM1 (warp tile 32x64), act, GEMM2 (32x32)
//   - 4 producer warps: coalesced gather into double-buffered X
// 128-row tiles; bar.sync 0,384 = tile boundary / buffer handoff,
// bar.sync 1,256 = consumer-only H barrier.
// ============================================================

#define XSTR 400   // 192 f16 + pad
#define HSTR 272   // 128 f16 + pad

#define SO_X0  0                        // 128 x XSTR = 51200
#define SO_X1  (128 * XSTR)             // 51200
#define SO_W1  (SO_X1 + 128 * XSTR)     // 51200
#define SO_W2  (SO_W1 + 128 * XSTR)     // 17408
#define SO_H   (SO_W2 + 64 * HSTR)      // 34816
#define SO_B1  (SO_H + 128 * HSTR)
#define SO_B2  (SO_B1 + 512)
#define SMEM_TOTAL (SO_B2 + 256 + 128)  // ~206.7 KB (< 227 KB)

#define BARX(id, cnt) \
    asm volatile("bar.sync %0, %1;" :: "r"(id), "r"(cnt) : "memory")

__device__ __forceinline__ uint32_t s2u(const void* p) {
    uint32_t a;
    asm("{ .reg .u64 t; cvta.to.shared.u64 t, %1; cvt.u32.u64 %0, t; }"
        : "=r"(a) : "l"(p));
    return a;
}

__device__ __forceinline__ uint32_t pkh2(float lo, float hi) {
    uint32_t r;
    asm("cvt.rn.f16x2.f32 %0, %1, %2;" : "=r"(r) : "f"(hi), "f"(lo));
    return r;
}

__device__ __forceinline__ void ldm4(uint32_t* r, uint32_t addr) {
    asm volatile("ldmatrix.sync.aligned.m8n8.x4.shared.b16 {%0,%1,%2,%3}, [%4];"
                 : "=r"(r[0]), "=r"(r[1]), "=r"(r[2]), "=r"(r[3]) : "r"(addr));
}

__device__ __forceinline__ void mma16816(float* d, const uint32_t* a,
                                         uint32_t b0, uint32_t b1) {
    asm volatile(
        "mma.sync.aligned.m16n8k16.row.col.f32.f16.f16.f32 "
        "{%0,%1,%2,%3}, {%4,%5,%6,%7}, {%8,%9}, {%0,%1,%2,%3};"
        : "+f"(d[0]), "+f"(d[1]), "+f"(d[2]), "+f"(d[3])
        : "r"(a[0]), "r"(a[1]), "r"(a[2]), "r"(a[3]), "r"(b0), "r"(b1));
}

// shifted softplus: softplus(x) - ln2 = max(x,0) + ln(1+e^{-|x|}) - ln2
__device__ __forceinline__ float ssp(float x) {
    float e = __expf(-fabsf(x));
    float l = __log2f(1.0f + e);
    return fmaxf(x, 0.0f) + 0.6931471805599453f * (l - 1.0f);
}

__global__ void __launch_bounds__(384, 1)
edge_update_kernel(const float* __restrict__ edge_state,
                   const int* __restrict__ edges,
                   const float* __restrict__ node_state,
                   const float* __restrict__ W1, const float* __restrict__ b1,
                   const float* __restrict__ W2, const float* __restrict__ b2,
                   float* __restrict__ out, int E) {
    extern __shared__ __align__(128) char smem[];
    uint32_t sb = s2u(smem);
    int tid = threadIdx.x;
    int lane = tid & 31, w = tid >> 5;

    // ---- one-time: stage weights (f32 -> f16) + biases into SMEM ----
    for (int i = tid; i < 128 * 192; i += 384) {
        int n = i / 192, k = i - n * 192;
        *(half*)(smem + SO_W1 + n * XSTR + k * 2) = __float2half_rn(W1[i]);
    }
    for (int i = tid; i < 64 * 128; i += 384) {
        int n = i >> 7, k = i & 127;
        *(half*)(smem + SO_W2 + n * HSTR + k * 2) = __float2half_rn(W2[i]);
    }
    if (tid < 128) ((float*)(smem + SO_B1))[tid] = b1[tid];
    if (tid < 64)  ((float*)(smem + SO_B2))[tid] = b2[tid];
    BARX(0, 384);   // staging visible to everyone

    const int ntiles = (E + 127) >> 7;
    const int g_half = lane >> 4;        // gather: row parity within pair
    const int g_li   = lane & 15;        // gather: float4 index in segment

    if (w >= 8) {
        // ===================== PRODUCER (warps 8-11) =====================
        const int pw = w - 8;            // 0..3, owns rows [32pw, 32pw+32)
        // prologue: fill X0 for first tile
        {
            long long t = blockIdx.x;
#pragma unroll 4
            for (int i2 = 0; i2 < 16; i2++) {
                int row = pw * 32 + i2 * 2 + g_half;
                long long e = t * 128 + row;
                long long ec = (e < E) ? e : (long long)(E - 1);
                int2 np2 = ((const int2*)edges)[ec];
                uint32_t xr = sb + SO_X0 + (uint32_t)row * XSTR + (uint32_t)g_li * 8u;
                float4 v0 = ((const float4*)(node_state + (long long)np2.x * 64))[g_li];
                float4 v1 = ((const float4*)(node_state + (long long)np2.y * 64))[g_li];
                float4 v2 = __ldcs((const float4*)(edge_state + ec * 64) + g_li);
                uint32_t a0 = pkh2(v0.x, v0.y), a1 = pkh2(v0.z, v0.w);
                uint32_t c0 = pkh2(v1.x, v1.y), c1 = pkh2(v1.z, v1.w);
                uint32_t d0 = pkh2(v2.x, v2.y), d1 = pkh2(v2.z, v2.w);
                asm volatile("st.shared.v2.b32 [%0], {%1,%2};"
                             :: "r"(xr), "r"(a0), "r"(a1) : "memory");
                asm volatile("st.shared.v2.b32 [%0], {%1,%2};"
                             :: "r"(xr + 128), "r"(c0), "r"(c1) : "memory");
                asm volatile("st.shared.v2.b32 [%0], {%1,%2};"
                             :: "r"(xr + 256), "r"(d0), "r"(d1) : "memory");
            }
        }
        int it = 0;
        for (long long t = blockIdx.x; t < ntiles; t += gridDim.x, it++) {
            BARX(0, 384);   // publish buf[it&1]; prior consumer reads done
            long long tn = t + gridDim.x;
            if (tn < ntiles) {
                uint32_t xb = (it & 1) ? (sb + SO_X0) : (sb + SO_X1); // (it+1)&1
#pragma unroll 4
                for (int i2 = 0; i2 < 16; i2++) {
                    int row = pw * 32 + i2 * 2 + g_half;
                    long long e = tn * 128 + row;
                    long long ec = (e < E) ? e : (long long)(E - 1);
                    int2 np2 = ((const int2*)edges)[ec];
                    uint32_t xr = xb + (uint32_t)row * XSTR + (uint32_t)g_li * 8u;
                    float4 v0 = ((const float4*)(node_state + (long long)np2.x * 64))[g_li];
                    float4 v1 = ((const float4*)(node_state + (long long)np2.y * 64))[g_li];
                    float4 v2 = __ldcs((const float4*)(edge_state + ec * 64) + g_li);
                    uint32_t a0 = pkh2(v0.x, v0.y), a1 = pkh2(v0.z, v0.w);
                    uint32_t c0 = pkh2(v1.x, v1.y), c1 = pkh2(v1.z, v1.w);
                    uint32_t d0 = pkh2(v2.x, v2.y), d1 = pkh2(v2.z, v2.w);
                    asm volatile("st.shared.v2.b32 [%0], {%1,%2};"
                                 :: "r"(xr), "r"(a0), "r"(a1) : "memory");
                    asm volatile("st.shared.v2.b32 [%0], {%1,%2};"
                                 :: "r"(xr + 128), "r"(c0), "r"(c1) : "memory");
                    asm volatile("st.shared.v2.b32 [%0], {%1,%2};"
                                 :: "r"(xr + 256), "r"(d0), "r"(d1) : "memory");
                }
            }
        }
    } else {
        // ===================== CONSUMER (warps 0-7) =====================
        const int m0  = (w & 3) * 32;   // 32 rows per warp
        const int n0  = (w >> 2) * 64;  // GEMM1: 64 cols per warp
        const int n02 = (w >> 2) * 32;  // GEMM2: 32 cols per warp

        float2 b1v[8], b2v[4];
        {
            const float* b1s = (const float*)(smem + SO_B1);
            const float* b2s = (const float*)(smem + SO_B2);
            int cb = 2 * (lane & 3);
#pragma unroll
            for (int nt = 0; nt < 8; nt++) {
                int c = n0 + nt * 8 + cb;
                b1v[nt] = make_float2(b1s[c], b1s[c + 1]);
            }
#pragma unroll
            for (int nt = 0; nt < 4; nt++) {
                int c = n02 + nt * 8 + cb;
                b2v[nt] = make_float2(b2s[c], b2s[c + 1]);
            }
        }

        const int a_r = lane & 15;
        const int a_c = (lane >> 4) << 3;
        const int b_r = ((lane >> 4) << 3) + (lane & 7);
        const int b_c = ((lane >> 3) & 1) << 3;

        // X ldmatrix offsets (relative; add buffer base per iteration)
        uint32_t aXo[2], aH[2], bW1[4], bW2[2];
#pragma unroll
        for (int mt = 0; mt < 2; mt++) {
            aXo[mt] = (uint32_t)(m0 + mt * 16 + a_r) * XSTR + a_c * 2;
            aH[mt]  = sb + SO_H + (uint32_t)(m0 + mt * 16 + a_r) * HSTR + a_c * 2;
        }
#pragma unroll
        for (int np = 0; np < 4; np++)
            bW1[np] = sb + SO_W1 + (uint32_t)(n0 + np * 16 + b_r) * XSTR + b_c * 2;
#pragma unroll
        for (int np = 0; np < 2; np++)
            bW2[np] = sb + SO_W2 + (uint32_t)(n02 + np * 16 + b_r) * HSTR + b_c * 2;

        const int act_r = lane >> 2;
        const int act_c = 2 * (lane & 3);

        int it = 0;
        for (long long t = blockIdx.x; t < ntiles; t += gridDim.x, it++) {
            BARX(0, 384);   // X buf[it&1] ready
            uint32_t xb = (it & 1) ? (sb + SO_X1) : (sb + SO_X0);

            // ============ GEMM1: 32x64, K=192 ============
            float acc[2][8][4];
#pragma unroll
            for (int mt = 0; mt < 2; mt++)
#pragma unroll
                for (int nt = 0; nt < 8; nt++)
#pragma unroll
                    for (int q = 0; q < 4; q++) acc[mt][nt][q] = 0.0f;

#pragma unroll
            for (int k = 0; k < 12; k++) {
                uint32_t A0[4], A1[4], B[4][4];
                ldm4(A0, xb + aXo[0] + k * 32);
                ldm4(A1, xb + aXo[1] + k * 32);
#pragma unroll
                for (int np = 0; np < 4; np++) ldm4(B[np], bW1[np] + k * 32);
#pragma unroll
                for (int np = 0; np < 4; np++) {
#pragma unroll
                    for (int h = 0; h < 2; h++) {
                        mma16816(acc[0][np * 2 + h], A0, B[np][2 * h], B[np][2 * h + 1]);
                        mma16816(acc[1][np * 2 + h], A1, B[np][2 * h], B[np][2 * h + 1]);
                    }
                }
            }

            // ============ activation -> f16 H ============
#pragma unroll
            for (int mt = 0; mt < 2; mt++) {
                uint32_t ha = sb + SO_H
                            + (uint32_t)(m0 + mt * 16 + act_r) * HSTR
                            + (uint32_t)(n0 + act_c) * 2;
#pragma unroll
                for (int nt = 0; nt < 8; nt++) {
                    float x0 = acc[mt][nt][0] + b1v[nt].x;
                    float x1 = acc[mt][nt][1] + b1v[nt].y;
                    float x2 = acc[mt][nt][2] + b1v[nt].x;
                    float x3 = acc[mt][nt][3] + b1v[nt].y;
                    uint32_t h01 = pkh2(ssp(x0), ssp(x1));
                    uint32_t h23 = pkh2(ssp(x2), ssp(x3));
                    asm volatile("st.shared.b32 [%0], %1;"
                                 :: "r"(ha + nt * 16), "r"(h01) : "memory");
                    asm volatile("st.shared.b32 [%0], %1;"
                                 :: "r"(ha + nt * 16 + 8 * HSTR), "r"(h23) : "memory");
                }
            }
            BARX(1, 256);   // consumer-only: H ready

            // ============ GEMM2: 32x32, K=128 ============
            float acc2[2][4][4];
#pragma unroll
            for (int mt = 0; mt < 2; mt++)
#pragma unroll
                for (int nt = 0; nt < 4; nt++)
#pragma unroll
                    for (int q = 0; q < 4; q++) acc2[mt][nt][q] = 0.0f;

#pragma unroll
            for (int k = 0; k < 8; k++) {
                uint32_t A0[4], A1[4], B[2][4];
                ldm4(A0, aH[0] + k * 32);
                ldm4(A1, aH[1] + k * 32);
                ldm4(B[0], bW2[0] + k * 32);
                ldm4(B[1], bW2[1] + k * 32);
#pragma unroll
                for (int np = 0; np < 2; np++) {
#pragma unroll
                    for (int h = 0; h < 2; h++) {
                        mma16816(acc2[0][np * 2 + h], A0, B[np][2 * h], B[np][2 * h + 1]);
                        mma16816(acc2[1][np * 2 + h], A1, B[np][2 * h], B[np][2 * h + 1]);
                    }
                }
            }

            // ============ epilogue: out = D2 + b2 (streaming) ============
            {
                long long ebase = t * 128 + m0 + act_r;
#pragma unroll
                for (int mt = 0; mt < 2; mt++) {
                    long long r0e = ebase + mt * 16;
#pragma unroll
                    for (int nt = 0; nt < 4; nt++) {
                        int c = n02 + nt * 8 + act_c;
                        if (r0e < E) {
                            float2 v;
                            v.x = acc2[mt][nt][0] + b2v[nt].x;
                            v.y = acc2[mt][nt][1] + b2v[nt].y;
                            __stcs((float2*)(out + r0e * 64 + c), v);
                        }
                        if (r0e + 8 < E) {
                            float2 v;
                            v.x = acc2[mt][nt][2] + b2v[nt].x;
                            v.y = acc2[mt][nt][3] + b2v[nt].y;
                            __stcs((float2*)(out + (r0e + 8) * 64 + c), v);
                        }
                    }
                }
            }
        }
    }
}

extern "C" void kernel_launch(void* const* d_in, const int* in_sizes, int n_in,
                              void* d_out, int out_size) {
    const float* edge_state = (const float*)d_in[0];
    const int*   edges      = (const int*)d_in[1];
    const float* node_state = (const float*)d_in[2];
    const float* W1         = (const float*)d_in[3];
    const float* b1         = (const float*)d_in[4];
    const float* W2         = (const float*)d_in[5];
    const float* b2         = (const float*)d_in[6];
    float*       out        = (float*)d_out;
    int E = in_sizes[0] / 64;

    cudaFuncSetAttribute(edge_update_kernel,
                         cudaFuncAttributeMaxDynamicSharedMemorySize, SMEM_TOTAL);
    edge_update_kernel<<<148, 384, SMEM_TOTAL>>>(edge_state, edges, node_state,
                                                 W1, b1, W2, b2, out, E);
}